// round 3
// baseline (speedup 1.0000x reference)
#include <cuda_runtime.h>
#include <math.h>

#define HB 4
#define CC 192
#define HW 65536
#define HW2 16384
#define HEADS 6
#define CHD 32

// ---------------- static scratch (two big buffers + small) ----------------
__device__ float g_A[100663296];      // 4*384*65536 floats (402 MB)
__device__ float g_B[100663296];      // 402 MB
__device__ float g_invq[768];
__device__ float g_invk[768];
__device__ float g_S[24 * 1024];
__device__ float g_A0[24 * 1024];
__device__ float g_part[32 * 24 * 1024];

// ---------------- generic 1x1 conv (channel-major GEMM) ----------------
// out[g][oc][p] = sum_ic W[oc][ic] * in[g][ic][p] (+ resid[g][oc][p])
// grid: (P/256, OC/64, G), block 256
__global__ void conv1x1_kernel(const float* __restrict__ X, const float* __restrict__ Wm,
                               const float* __restrict__ resid, float* __restrict__ Y,
                               int IC, int OC, int P)
{
    const int g = blockIdx.z;
    const int oc0 = blockIdx.y * 64;
    const int p0 = blockIdx.x * 256;
    const float* Xg = X + (size_t)g * IC * P;
    float* Yg = Y + (size_t)g * OC * P;

    __shared__ float Ws[16][64];
    __shared__ float Xs[16][256];

    const int tid = threadIdx.x;
    const int tx = tid & 15;
    const int ty = tid >> 4;

    float acc[4][16];
#pragma unroll
    for (int i = 0; i < 4; i++)
#pragma unroll
        for (int j = 0; j < 16; j++) acc[i][j] = 0.f;

    for (int k0 = 0; k0 < IC; k0 += 16) {
#pragma unroll
        for (int r = 0; r < 4; r++) {
            int e = tid + r * 256;
            int kk = e >> 6, oc = e & 63;
            Ws[kk][oc] = Wm[(size_t)(oc0 + oc) * IC + k0 + kk];
        }
#pragma unroll
        for (int r = 0; r < 16; r++) {
            int e = tid + r * 256;
            int kk = e >> 8, pp = e & 255;
            Xs[kk][pp] = Xg[(size_t)(k0 + kk) * P + p0 + pp];
        }
        __syncthreads();
#pragma unroll
        for (int kk = 0; kk < 16; kk++) {
            float a[4], b[16];
#pragma unroll
            for (int i = 0; i < 4; i++) a[i] = Ws[kk][ty * 4 + i];
#pragma unroll
            for (int j = 0; j < 16; j++) b[j] = Xs[kk][tx + j * 16];
#pragma unroll
            for (int i = 0; i < 4; i++)
#pragma unroll
                for (int j = 0; j < 16; j++) acc[i][j] += a[i] * b[j];
        }
        __syncthreads();
    }
#pragma unroll
    for (int i = 0; i < 4; i++) {
        int oc = oc0 + ty * 4 + i;
#pragma unroll
        for (int j = 0; j < 16; j++) {
            int p = p0 + tx + j * 16;
            float v = acc[i][j];
            if (resid) v += resid[((size_t)g * OC + oc) * P + p];
            Yg[(size_t)oc * P + p] = v;
        }
    }
}

// ---------------- depthwise 3x3, SAME pad ----------------
__global__ void dw3_kernel(const float* __restrict__ in, const float* __restrict__ w9,
                           float* __restrict__ out, int C, int Hn, int Wn, int total)
{
    int idx = blockIdx.x * 256 + threadIdx.x;
    if (idx >= total) return;
    int x = idx % Wn;
    int t = idx / Wn;
    int y = t % Hn;
    int c = (t / Hn) % C;
    const float* wp = w9 + c * 9;
    const float* p = in + (size_t)(idx - x - y * Wn);
    float s = 0.f;
#pragma unroll
    for (int dy = -1; dy <= 1; dy++) {
        int yy = y + dy;
        if ((unsigned)yy >= (unsigned)Hn) continue;
#pragma unroll
        for (int dx = -1; dx <= 1; dx++) {
            int xx = x + dx;
            if ((unsigned)xx >= (unsigned)Wn) continue;
            s += wp[(dy + 1) * 3 + (dx + 1)] * p[yy * Wn + xx];
        }
    }
    out[idx] = s;
}

// ---------------- level-0 row norms (over n = 65536) ----------------
__global__ void rownorm_kernel(const float* __restrict__ base, int chanPerBatch,
                               float* __restrict__ inv)
{
    int row = blockIdx.x;              // 0..767  (b*192 + cc)
    int b = row / CC, c = row % CC;
    const float* p = base + ((size_t)b * chanPerBatch + c) * HW;
    float s = 0.f;
    for (int i = threadIdx.x; i < HW; i += 256) { float v = p[i]; s += v * v; }
    __shared__ float red[256];
    red[threadIdx.x] = s;
    __syncthreads();
    for (int o = 128; o; o >>= 1) {
        if (threadIdx.x < o) red[threadIdx.x] += red[threadIdx.x + o];
        __syncthreads();
    }
    if (threadIdx.x == 0) inv[row] = 1.f / fmaxf(sqrtf(red[0]), 1e-12f);
}

// ---------------- level-0 S = q k^T (partial, deterministic) ----------------
__global__ void s_accum_kernel(const float* __restrict__ q, const float* __restrict__ kv,
                               float* __restrict__ part)
{
    int bh = blockIdx.y;
    int b = bh / HEADS, h = bh % HEADS;
    const float* qb = q + ((size_t)b * CC + h * CHD) * HW;
    const float* kb = kv + ((size_t)b * 2 * CC + h * CHD) * HW;
    int n0 = blockIdx.x * 2048;
    __shared__ float qt[32][65], kt[32][65];
    float acc[4] = {0.f, 0.f, 0.f, 0.f};
    int tid = threadIdx.x;
    for (int ns = 0; ns < 2048; ns += 64) {
#pragma unroll
        for (int r = 0; r < 8; r++) {
            int e = tid + r * 256;
            int c = e >> 6, nn = e & 63;
            qt[c][nn] = qb[(size_t)c * HW + n0 + ns + nn];
            kt[c][nn] = kb[(size_t)c * HW + n0 + ns + nn];
        }
        __syncthreads();
#pragma unroll
        for (int i = 0; i < 4; i++) {
            int pr = i * 256 + tid;
            int c = pr >> 5, d = pr & 31;
            float a = 0.f;
#pragma unroll
            for (int kk = 0; kk < 64; kk++) a += qt[c][kk] * kt[d][kk];
            acc[i] += a;
        }
        __syncthreads();
    }
#pragma unroll
    for (int i = 0; i < 4; i++) {
        int pr = i * 256 + tid;
        part[((size_t)blockIdx.x * 24 + bh) * 1024 + pr] = acc[i];
    }
}

__global__ void s_reduce_kernel(const float* __restrict__ part, float* __restrict__ S)
{
    int idx = blockIdx.x * 256 + threadIdx.x;   // 24576 entries
    float s = 0.f;
    for (int ck = 0; ck < 32; ck++) s += part[(size_t)ck * 24576 + idx];
    S[idx] = s;
}

// ---------------- level-0 softmax (32x32 per (b,h)) ----------------
__global__ void softmax0_kernel(const float* __restrict__ S, const float* __restrict__ invq,
                                const float* __restrict__ invk, const float* __restrict__ temp0,
                                float* __restrict__ A)
{
    int bh = blockIdx.x;
    int b = bh / HEADS, h = bh % HEADS;
    int c = threadIdx.y, d = threadIdx.x;
    float v = S[bh * 1024 + c * 32 + d] * invq[b * CC + h * CHD + c] *
              invk[b * CC + h * CHD + d] * temp0[h];
    float m = v;
#pragma unroll
    for (int o = 16; o; o >>= 1) m = fmaxf(m, __shfl_xor_sync(0xffffffffu, m, o));
    float e = expf(v - m);
    float s = e;
#pragma unroll
    for (int o = 16; o; o >>= 1) s += __shfl_xor_sync(0xffffffffu, s, o);
    A[bh * 1024 + c * 32 + d] = e / s;
}

// ---------------- level-0 out = A @ v ----------------
__global__ void out0n_kernel(const float* __restrict__ A, const float* __restrict__ kv,
                             float* __restrict__ out)
{
    int bh = blockIdx.y;
    int b = bh / HEADS, h = bh % HEADS;
    __shared__ float As[32][33];
    int tid = threadIdx.x;
    for (int e = tid; e < 1024; e += 256) As[e >> 5][e & 31] = A[bh * 1024 + e];
    __syncthreads();
    int n = blockIdx.x * 256 + tid;
    const float* vb = kv + ((size_t)b * 2 * CC + CC + h * CHD) * HW + n;
    float vr[32];
#pragma unroll
    for (int d = 0; d < 32; d++) vr[d] = vb[(size_t)d * HW];
    float* ob = out + ((size_t)b * CC + h * CHD) * HW + n;
#pragma unroll
    for (int c = 0; c < 32; c++) {
        float s = 0.f;
#pragma unroll
        for (int d = 0; d < 32; d++) s += As[c][d] * vr[d];
        ob[(size_t)c * HW] = s;
    }
}

// ---------------- avg pool 2x2 ----------------
__global__ void avgpool_kernel(const float* __restrict__ x, float* __restrict__ o)
{
    int idx = blockIdx.x * 256 + threadIdx.x;
    if (idx >= HB * CC * HW2) return;
    int xx = idx & 127;
    int yy = (idx >> 7) & 127;
    int bc = idx >> 14;
    const float* p = x + (size_t)bc * HW + (yy * 2) * 256 + xx * 2;
    o[idx] = 0.25f * (p[0] + p[1] + p[256] + p[257]);
}

// ---------------- q1 regrouping gather: (4,C,256,256) -> (16,C,128,128) ----------------
__global__ void q1gather_kernel(const float* __restrict__ qt, float* __restrict__ qr)
{
    int idx = blockIdx.x * 256 + threadIdx.x;
    if (idx >= 16 * CC * HW2) return;
    int x = idx & 127;
    int y = (idx >> 7) & 127;
    int c = (idx >> 14) % CC;
    int img = idx / (CC * HW2);
    int whp = y >> 3, yy = y & 7, wwp = x >> 3, xx = x & 7;
    int k = img & 3, b = img >> 2;
    int wh = 8 * k + (whp >> 1);
    int ww = ((whp & 1) << 4) + wwp;
    int sy = wh * 8 + yy, sx = ww * 8 + xx;
    qr[idx] = qt[((size_t)b * CC + c) * HW + sy * 256 + sx];
}

// ---------------- shifted-window cosine attention ----------------
// grid 4096 blocks (one per q window), 256 threads, big dynamic smem.
__global__ void winattn_kernel(const float* __restrict__ qg, const float* __restrict__ kvg,
                               const float* __restrict__ rpbt, const float* __restrict__ temp1,
                               float* __restrict__ outg)
{
    extern __shared__ float sm[];
    float* qs = sm;                       // 192*64
    float* ks = qs + 192 * 64;            // 192*64
    float* vs = ks + 192 * 64;            // 192*64
    float* os = vs + 192 * 64;            // 192*64
    float* at = os + 192 * 64;            // 64*65 (padded)
    float* inq = at + 64 * 65;            // 6*64
    float* ink = inq + 384;               // 6*64

    int win = blockIdx.x;
    int img = win >> 8;
    int loc = win & 255;
    int whp = loc >> 4, wwp = loc & 15;
    int kwin = win >> 2;
    int bk = kwin >> 8;
    int loc2 = kwin & 255;
    int gh = loc2 >> 4, gw = loc2 & 15;
    int tid = threadIdx.x;

    // load q window (roll -4,-4 folded into indexing)
    for (int e = tid; e < 192 * 64; e += 256) {
        int c = e >> 6, t = e & 63;
        int yy = t >> 3, xx = t & 7;
        int y = (whp * 8 + yy + 4) & 127;
        int x = (wwp * 8 + xx + 4) & 127;
        qs[e] = qg[((size_t)img * CC + c) * HW2 + y * 128 + x];
    }
    // load k,v window
    for (int e = tid; e < 192 * 64; e += 256) {
        int c = e >> 6, t = e & 63;
        int yy = t >> 3, xx = t & 7;
        int y = (gh * 8 + yy + 4) & 127;
        int x = (gw * 8 + xx + 4) & 127;
        size_t base = ((size_t)bk * 2 * CC + c) * HW2 + y * 128 + x;
        ks[e] = kvg[base];
        vs[e] = kvg[base + (size_t)CC * HW2];
    }
    __syncthreads();

    // per (head, token) norms over 32 channels
    for (int e = tid; e < 384; e += 256) {
        int h = e >> 6, t = e & 63;
        float sq = 0.f, sk = 0.f;
#pragma unroll
        for (int i = 0; i < 32; i++) {
            float a = qs[(h * 32 + i) * 64 + t]; sq += a * a;
            float b = ks[(h * 32 + i) * 64 + t]; sk += b * b;
        }
        inq[e] = 1.f / fmaxf(sqrtf(sq), 1e-12f);
        ink[e] = 1.f / fmaxf(sqrtf(sk), 1e-12f);
    }
    __syncthreads();

    for (int h = 0; h < HEADS; h++) {
        float tmp = temp1[h];
        // attn logits
        for (int e = tid; e < 4096; e += 256) {
            int n = e >> 6, m = e & 63;
            const float* qp = qs + (h * 32) * 64 + n;
            const float* kp = ks + (h * 32) * 64 + m;
            float s = 0.f;
#pragma unroll
            for (int i = 0; i < 32; i++) s += qp[i * 64] * kp[i * 64];
            s = s * inq[h * 64 + n] * ink[h * 64 + m] * tmp;
            int yn = n >> 3, xn = n & 7, ym = m >> 3, xm = m & 7;
            int ridx = (yn - ym + 7) * 15 + (xn - xm + 7);
            s += rpbt[ridx * HEADS + h];
            int pyn = gh * 8 + yn, pxn = gw * 8 + xn;
            int pym = gh * 8 + ym, pxm = gw * 8 + xm;
            int ln = (pyn < 120 ? 0 : (pyn < 124 ? 1 : 2)) * 3 + (pxn < 120 ? 0 : (pxn < 124 ? 1 : 2));
            int lm = (pym < 120 ? 0 : (pym < 124 ? 1 : 2)) * 3 + (pxm < 120 ? 0 : (pxm < 124 ? 1 : 2));
            if (ln != lm) s -= 100.f;
            at[n * 65 + m] = s;
        }
        __syncthreads();
        // row softmax (8 warps, 8 rows each)
        {
            int wid = tid >> 5, lane = tid & 31;
            for (int r = wid; r < 64; r += 8) {
                float v0 = at[r * 65 + lane], v1 = at[r * 65 + lane + 32];
                float mx = fmaxf(v0, v1);
#pragma unroll
                for (int o = 16; o; o >>= 1) mx = fmaxf(mx, __shfl_xor_sync(0xffffffffu, mx, o));
                v0 = expf(v0 - mx);
                v1 = expf(v1 - mx);
                float su = v0 + v1;
#pragma unroll
                for (int o = 16; o; o >>= 1) su += __shfl_xor_sync(0xffffffffu, su, o);
                float inv = 1.f / su;
                at[r * 65 + lane] = v0 * inv;
                at[r * 65 + lane + 32] = v1 * inv;
            }
        }
        __syncthreads();
        // out = attn @ v  (i outer so warp scans n -> conflict-free)
        for (int e = tid; e < 2048; e += 256) {
            int i = e >> 6, n = e & 63;
            const float* ap = at + n * 65;
            const float* vp = vs + (h * 32 + i) * 64;
            float s = 0.f;
#pragma unroll
            for (int m = 0; m < 64; m++) s += ap[m] * vp[m];
            os[(h * 32 + i) * 64 + n] = s;
        }
        __syncthreads();
    }
    // write channel-major tokens: outg[c][win*64 + t]
    for (int e = tid; e < 192 * 64; e += 256) {
        int c = e >> 6, t = e & 63;
        outg[(size_t)c * 262144 + (size_t)win * 64 + t] = os[e];
    }
}

// ---------------- proj1 result scatter-add (window_reverse + roll +4) ----------------
__global__ void scatter1_kernel(const float* __restrict__ pin, float* __restrict__ out)
{
    int idx = blockIdx.x * 256 + threadIdx.x;
    if (idx >= CC * 262144) return;
    int p = idx & 262143;
    int cc = idx >> 18;
    int w = p >> 6;
    int t = p & 63;
    int yy = t >> 3, xx = t & 7;
    int b = w >> 10;
    int wh = (w >> 5) & 31;
    int wn = w & 31;
    int y = (wh * 8 + yy + 4) & 255;
    int x = (wn * 8 + xx + 4) & 255;
    out[((size_t)b * CC + cc) * HW + y * 256 + x] += pin[idx];
}

// ==================================================================
extern "C" void kernel_launch(void* const* d_in, const int* in_sizes, int n_in,
                              void* d_out, int out_size)
{
    const float* x      = (const float*)d_in[0];
    const float* Wq0    = (const float*)d_in[1];
    const float* Wqdw0  = (const float*)d_in[2];
    const float* Wkv0   = (const float*)d_in[3];
    const float* Wkvdw0 = (const float*)d_in[4];
    const float* Wq1    = (const float*)d_in[5];
    const float* Wqdw1  = (const float*)d_in[6];
    const float* Wkv1   = (const float*)d_in[7];
    const float* Wkvdw1 = (const float*)d_in[8];
    const float* Wproj0 = (const float*)d_in[9];
    const float* Wproj1 = (const float*)d_in[10];
    const float* temp0  = (const float*)d_in[11];
    const float* temp1  = (const float*)d_in[12];
    const float* rpbt   = (const float*)d_in[13];
    const float* Wds    = (const float*)d_in[14];
    float* out = (float*)d_out;

    float *A, *B, *invq, *invk, *Sb, *A0, *part;
    cudaGetSymbolAddress((void**)&A, g_A);
    cudaGetSymbolAddress((void**)&B, g_B);
    cudaGetSymbolAddress((void**)&invq, g_invq);
    cudaGetSymbolAddress((void**)&invk, g_invk);
    cudaGetSymbolAddress((void**)&Sb, g_S);
    cudaGetSymbolAddress((void**)&A0, g_A0);
    cudaGetSymbolAddress((void**)&part, g_part);

    const size_t OFF50 = 50331648;   // 4*192*65536
    float* A2  = A + OFF50;
    float* B12 = B + 12582912;       // xds
    float* B25 = B + 25165824;       // kv1t
    float* B50 = B + 50331648;       // kv1

    // ---------- level 0 ----------
    // kv0t -> A ; kv0 = dw3 -> B
    conv1x1_kernel<<<dim3(256, 6, 4), 256>>>(x, Wkv0, nullptr, A, CC, 2 * CC, HW);
    dw3_kernel<<<(4 * 2 * CC * HW) / 256, 256>>>(A, Wkvdw0, B, 2 * CC, 256, 256, 4 * 2 * CC * HW);
    // q0t -> A[0:] ; q0 = dw3 -> A[50M:]
    conv1x1_kernel<<<dim3(256, 3, 4), 256>>>(x, Wq0, nullptr, A, CC, CC, HW);
    dw3_kernel<<<(4 * CC * HW) / 256, 256>>>(A, Wqdw0, A2, CC, 256, 256, 4 * CC * HW);
    // norms
    rownorm_kernel<<<768, 256>>>(A2, CC, invq);
    rownorm_kernel<<<768, 256>>>(B, 2 * CC, invk);
    // S partials + reduce + softmax
    s_accum_kernel<<<dim3(32, 24), 256>>>(A2, B, part);
    s_reduce_kernel<<<96, 256>>>(part, Sb);
    softmax0_kernel<<<24, dim3(32, 32)>>>(Sb, invq, invk, temp0, A0);
    // out0n -> A[0:] ; proj0 -> d_out (full write, initializes output)
    out0n_kernel<<<dim3(256, 24), 256>>>(A0, B, A);
    conv1x1_kernel<<<dim3(256, 3, 4), 256>>>(A, Wproj0, nullptr, out, CC, CC, HW);

    // ---------- level 1 ----------  (A, B free now)
    // pool -> B[0:] ; xds = pool + Wds@pool -> B12
    avgpool_kernel<<<(4 * CC * HW2) / 256, 256>>>(x, B);
    conv1x1_kernel<<<dim3(64, 3, 4), 256>>>(B, Wds, B, B12, CC, CC, HW2);
    // kv1t = Wkv1 @ xds -> B25 ; kv1 = dw3 -> B50
    conv1x1_kernel<<<dim3(64, 6, 4), 256>>>(B12, Wkv1, nullptr, B25, CC, 2 * CC, HW2);
    dw3_kernel<<<(4 * 2 * CC * HW2) / 256, 256>>>(B25, Wkvdw1, B50, 2 * CC, 128, 128, 4 * 2 * CC * HW2);
    // q1t = Wq1 @ x -> A[0:] ; regroup -> A[50M:] ; q1 = dw3 -> A[0:]
    conv1x1_kernel<<<dim3(256, 3, 4), 256>>>(x, Wq1, nullptr, A, CC, CC, HW);
    q1gather_kernel<<<(16 * CC * HW2) / 256, 256>>>(A, A2);
    dw3_kernel<<<(16 * CC * HW2) / 256, 256>>>(A2, Wqdw1, A, CC, 128, 128, 16 * CC * HW2);
    // windowed attention -> B[0:] (channel-major tokens)
    {
        int smemBytes = (4 * 192 * 64 + 64 * 65 + 2 * 384) * 4;
        cudaFuncSetAttribute(winattn_kernel, cudaFuncAttributeMaxDynamicSharedMemorySize, smemBytes);
        winattn_kernel<<<4096, 256, smemBytes>>>(A, B50, rpbt, temp1, B);
    }
    // proj1 -> A[50M:] ; scatter-add into d_out
    conv1x1_kernel<<<dim3(1024, 3, 1), 256>>>(B, Wproj1, nullptr, A2, CC, CC, 262144);
    scatter1_kernel<<<(CC * 262144) / 256, 256>>>(A2, out);
}

// round 5
// speedup vs baseline: 1.3037x; 1.3037x over previous
#include <cuda_runtime.h>
#include <cuda_bf16.h>
#include <math.h>
#include <stdint.h>

#define HB 4
#define CC 192
#define HW 65536
#define HW2 16384
#define HEADS 6
#define CHD 32

// ---------------- static scratch (two big buffers + small) ----------------
__device__ float g_A[100663296];      // 402 MB
__device__ float g_B[100663296];      // 402 MB
__device__ float g_invq[768];
__device__ float g_invk[768];
__device__ float g_S[24 * 1024];
__device__ float g_A0[24 * 1024];
__device__ float g_part[32 * 24 * 1024];

// ================= bf16 helpers =================
__device__ __forceinline__ unsigned short bfb(float v) {
    __nv_bfloat16 b = __float2bfloat16(v);
    return *(unsigned short*)&b;
}
__device__ __forceinline__ float bff(unsigned short s) {
    __nv_bfloat16 b = *(__nv_bfloat16*)&s;
    return __bfloat162float(b);
}

__device__ __forceinline__ void mma16816(float* d, const uint32_t* a, const uint32_t* b) {
    asm volatile(
        "mma.sync.aligned.m16n8k16.row.col.f32.bf16.bf16.f32 "
        "{%0,%1,%2,%3}, {%4,%5,%6,%7}, {%8,%9}, {%0,%1,%2,%3};"
        : "+f"(d[0]), "+f"(d[1]), "+f"(d[2]), "+f"(d[3])
        : "r"(a[0]), "r"(a[1]), "r"(a[2]), "r"(a[3]), "r"(b[0]), "r"(b[1]));
}

// ---------------- tensor-core 1x1 conv GEMM (bf16 hi/lo split, mma.sync) ----------------
// Y[g][oc][p] = sum_ic W[oc][ic] X[g][ic][p] (+resid). grid(P/128, ceil(OC/128), G), 256 thr.
#define SK 40   // smem row stride (bf16 elems): banks row*20 -> conflict-free frag loads

__global__ void __launch_bounds__(256, 2)
mma_gemm_kernel(const float* __restrict__ X, const float* __restrict__ Wm,
                const float* __restrict__ resid, float* __restrict__ Y,
                int IC, int OC, int P)
{
    __shared__ __align__(16) unsigned short sb[4 * 128 * SK];   // Ahi,Alo,Bhi,Blo (40KB)
    unsigned short* Ahi = sb;
    unsigned short* Alo = sb + 128 * SK;
    unsigned short* Bhi = sb + 2 * 128 * SK;
    unsigned short* Blo = sb + 3 * 128 * SK;

    const int tid = threadIdx.x;
    const int warp = tid >> 5, lane = tid & 31;
    const int g4 = lane >> 2, t4 = lane & 3;
    const int wm = warp >> 1, wn = warp & 1;
    const int gz = blockIdx.z;
    const int oc0 = blockIdx.y * 128;
    const int p0 = blockIdx.x * 128;
    const float* Xg = X + (size_t)gz * IC * P;

    const int nrow = tid & 127;
    const int kg = tid >> 7;          // 0/1 : which 16-wide k slice this thread fills

    float acc[2][8][4];
#pragma unroll
    for (int mt = 0; mt < 2; mt++)
#pragma unroll
        for (int nt = 0; nt < 8; nt++)
#pragma unroll
            for (int e = 0; e < 4; e++) acc[mt][nt][e] = 0.f;

    const int KC = IC / 32;
    for (int kc = 0; kc < KC; kc++) {
        const int kbase = kc * 32 + kg * 16;
        // ---- A (weights) ----
        {
            float va[16];
            int oc = oc0 + nrow;
            if (oc < OC) {
                const float* wp = Wm + (size_t)oc * IC + kbase;
#pragma unroll
                for (int j4 = 0; j4 < 4; j4++) {
                    float4 v = *(const float4*)(wp + j4 * 4);
                    va[j4 * 4 + 0] = v.x; va[j4 * 4 + 1] = v.y;
                    va[j4 * 4 + 2] = v.z; va[j4 * 4 + 3] = v.w;
                }
            } else {
#pragma unroll
                for (int j = 0; j < 16; j++) va[j] = 0.f;
            }
#pragma unroll
            for (int j = 0; j < 8; j++) {
                float v0 = va[2 * j], v1 = va[2 * j + 1];
                unsigned short h0 = bfb(v0), h1 = bfb(v1);
                unsigned short l0 = bfb(v0 - bff(h0)), l1 = bfb(v1 - bff(h1));
                int off = nrow * SK + kg * 16 + 2 * j;
                *(uint32_t*)&Ahi[off] = (uint32_t)h0 | ((uint32_t)h1 << 16);
                *(uint32_t*)&Alo[off] = (uint32_t)l0 | ((uint32_t)l1 << 16);
            }
        }
        // ---- B (activations), transpose into [p][k] ----
        {
            float vb[16];
#pragma unroll
            for (int e = 0; e < 16; e++)
                vb[e] = Xg[(size_t)(kbase + e) * P + p0 + nrow];
#pragma unroll
            for (int j = 0; j < 8; j++) {
                float v0 = vb[2 * j], v1 = vb[2 * j + 1];
                unsigned short h0 = bfb(v0), h1 = bfb(v1);
                unsigned short l0 = bfb(v0 - bff(h0)), l1 = bfb(v1 - bff(h1));
                int off = nrow * SK + kg * 16 + 2 * j;
                *(uint32_t*)&Bhi[off] = (uint32_t)h0 | ((uint32_t)h1 << 16);
                *(uint32_t*)&Blo[off] = (uint32_t)l0 | ((uint32_t)l1 << 16);
            }
        }
        __syncthreads();

        // ---- compute: 2 k-steps of 16 ----
#pragma unroll
        for (int ks = 0; ks < 2; ks++) {
            const int k1 = ks * 16 + t4 * 2;
            const int k2 = k1 + 8;
            uint32_t ah[2][4], al[2][4];
#pragma unroll
            for (int mt = 0; mt < 2; mt++) {
                int r = wm * 32 + mt * 16 + g4;
                ah[mt][0] = *(const uint32_t*)&Ahi[r * SK + k1];
                ah[mt][1] = *(const uint32_t*)&Ahi[(r + 8) * SK + k1];
                ah[mt][2] = *(const uint32_t*)&Ahi[r * SK + k2];
                ah[mt][3] = *(const uint32_t*)&Ahi[(r + 8) * SK + k2];
                al[mt][0] = *(const uint32_t*)&Alo[r * SK + k1];
                al[mt][1] = *(const uint32_t*)&Alo[(r + 8) * SK + k1];
                al[mt][2] = *(const uint32_t*)&Alo[r * SK + k2];
                al[mt][3] = *(const uint32_t*)&Alo[(r + 8) * SK + k2];
            }
#pragma unroll
            for (int nt = 0; nt < 8; nt++) {
                int c = wn * 64 + nt * 8 + g4;
                uint32_t bh[2], bl[2];
                bh[0] = *(const uint32_t*)&Bhi[c * SK + k1];
                bh[1] = *(const uint32_t*)&Bhi[c * SK + k2];
                bl[0] = *(const uint32_t*)&Blo[c * SK + k1];
                bl[1] = *(const uint32_t*)&Blo[c * SK + k2];
                mma16816(acc[0][nt], ah[0], bh);
                mma16816(acc[1][nt], ah[1], bh);
                mma16816(acc[0][nt], ah[0], bl);
                mma16816(acc[1][nt], ah[1], bl);
                mma16816(acc[0][nt], al[0], bh);
                mma16816(acc[1][nt], al[1], bh);
            }
        }
        __syncthreads();
    }

    // ---- epilogue: direct stores (32B-sector aligned pairs) ----
#pragma unroll
    for (int mt = 0; mt < 2; mt++) {
        int r0 = oc0 + wm * 32 + mt * 16 + g4;
#pragma unroll
        for (int nt = 0; nt < 8; nt++) {
            int p = p0 + wn * 64 + nt * 8 + t4 * 2;
            if (r0 < OC) {
                size_t o = ((size_t)gz * OC + r0) * P + p;
                float v0 = acc[mt][nt][0], v1 = acc[mt][nt][1];
                if (resid) { v0 += resid[o]; v1 += resid[o + 1]; }
                Y[o] = v0; Y[o + 1] = v1;
            }
            int r1 = r0 + 8;
            if (r1 < OC) {
                size_t o = ((size_t)gz * OC + r1) * P + p;
                float v0 = acc[mt][nt][2], v1 = acc[mt][nt][3];
                if (resid) { v0 += resid[o]; v1 += resid[o + 1]; }
                Y[o] = v0; Y[o + 1] = v1;
            }
        }
    }
}

// ---------------- depthwise 3x3, SAME pad ----------------
__global__ void dw3_kernel(const float* __restrict__ in, const float* __restrict__ w9,
                           float* __restrict__ out, int C, int Hn, int Wn, int total)
{
    int idx = blockIdx.x * 256 + threadIdx.x;
    if (idx >= total) return;
    int x = idx % Wn;
    int t = idx / Wn;
    int y = t % Hn;
    int c = (t / Hn) % C;
    const float* wp = w9 + c * 9;
    const float* p = in + (size_t)(idx - x - y * Wn);
    float s = 0.f;
#pragma unroll
    for (int dy = -1; dy <= 1; dy++) {
        int yy = y + dy;
        if ((unsigned)yy >= (unsigned)Hn) continue;
#pragma unroll
        for (int dx = -1; dx <= 1; dx++) {
            int xx = x + dx;
            if ((unsigned)xx >= (unsigned)Wn) continue;
            s += wp[(dy + 1) * 3 + (dx + 1)] * p[yy * Wn + xx];
        }
    }
    out[idx] = s;
}

// ---------------- level-0 row norms (over n = 65536) ----------------
__global__ void rownorm_kernel(const float* __restrict__ base, int chanPerBatch,
                               float* __restrict__ inv)
{
    int row = blockIdx.x;
    int b = row / CC, c = row % CC;
    const float* p = base + ((size_t)b * chanPerBatch + c) * HW;
    float s = 0.f;
    for (int i = threadIdx.x; i < HW; i += 256) { float v = p[i]; s += v * v; }
    __shared__ float red[256];
    red[threadIdx.x] = s;
    __syncthreads();
    for (int o = 128; o; o >>= 1) {
        if (threadIdx.x < o) red[threadIdx.x] += red[threadIdx.x + o];
        __syncthreads();
    }
    if (threadIdx.x == 0) inv[row] = 1.f / fmaxf(sqrtf(red[0]), 1e-12f);
}

// ---------------- level-0 S = q k^T (partial, deterministic) ----------------
__global__ void s_accum_kernel(const float* __restrict__ q, const float* __restrict__ kv,
                               float* __restrict__ part)
{
    int bh = blockIdx.y;
    int b = bh / HEADS, h = bh % HEADS;
    const float* qb = q + ((size_t)b * CC + h * CHD) * HW;
    const float* kb = kv + ((size_t)b * 2 * CC + h * CHD) * HW;
    int n0 = blockIdx.x * 2048;
    __shared__ float qt[32][65], kt[32][65];
    float acc[4] = {0.f, 0.f, 0.f, 0.f};
    int tid = threadIdx.x;
    for (int ns = 0; ns < 2048; ns += 64) {
#pragma unroll
        for (int r = 0; r < 8; r++) {
            int e = tid + r * 256;
            int c = e >> 6, nn = e & 63;
            qt[c][nn] = qb[(size_t)c * HW + n0 + ns + nn];
            kt[c][nn] = kb[(size_t)c * HW + n0 + ns + nn];
        }
        __syncthreads();
#pragma unroll
        for (int i = 0; i < 4; i++) {
            int pr = i * 256 + tid;
            int c = pr >> 5, d = pr & 31;
            float a = 0.f;
#pragma unroll
            for (int kk = 0; kk < 64; kk++) a += qt[c][kk] * kt[d][kk];
            acc[i] += a;
        }
        __syncthreads();
    }
#pragma unroll
    for (int i = 0; i < 4; i++) {
        int pr = i * 256 + tid;
        part[((size_t)blockIdx.x * 24 + bh) * 1024 + pr] = acc[i];
    }
}

__global__ void s_reduce_kernel(const float* __restrict__ part, float* __restrict__ S)
{
    int idx = blockIdx.x * 256 + threadIdx.x;
    float s = 0.f;
    for (int ck = 0; ck < 32; ck++) s += part[(size_t)ck * 24576 + idx];
    S[idx] = s;
}

// ---------------- level-0 softmax (32x32 per (b,h)) ----------------
__global__ void softmax0_kernel(const float* __restrict__ S, const float* __restrict__ invq,
                                const float* __restrict__ invk, const float* __restrict__ temp0,
                                float* __restrict__ A)
{
    int bh = blockIdx.x;
    int b = bh / HEADS, h = bh % HEADS;
    int c = threadIdx.y, d = threadIdx.x;
    float v = S[bh * 1024 + c * 32 + d] * invq[b * CC + h * CHD + c] *
              invk[b * CC + h * CHD + d] * temp0[h];
    float m = v;
#pragma unroll
    for (int o = 16; o; o >>= 1) m = fmaxf(m, __shfl_xor_sync(0xffffffffu, m, o));
    float e = expf(v - m);
    float s = e;
#pragma unroll
    for (int o = 16; o; o >>= 1) s += __shfl_xor_sync(0xffffffffu, s, o);
    A[bh * 1024 + c * 32 + d] = e / s;
}

// ---------------- level-0 out = A @ v ----------------
__global__ void out0n_kernel(const float* __restrict__ A, const float* __restrict__ kv,
                             float* __restrict__ out)
{
    int bh = blockIdx.y;
    int b = bh / HEADS, h = bh % HEADS;
    __shared__ float As[32][33];
    int tid = threadIdx.x;
    for (int e = tid; e < 1024; e += 256) As[e >> 5][e & 31] = A[bh * 1024 + e];
    __syncthreads();
    int n = blockIdx.x * 256 + tid;
    const float* vb = kv + ((size_t)b * 2 * CC + CC + h * CHD) * HW + n;
    float vr[32];
#pragma unroll
    for (int d = 0; d < 32; d++) vr[d] = vb[(size_t)d * HW];
    float* ob = out + ((size_t)b * CC + h * CHD) * HW + n;
#pragma unroll
    for (int c = 0; c < 32; c++) {
        float s = 0.f;
#pragma unroll
        for (int d = 0; d < 32; d++) s += As[c][d] * vr[d];
        ob[(size_t)c * HW] = s;
    }
}

// ---------------- avg pool 2x2 ----------------
__global__ void avgpool_kernel(const float* __restrict__ x, float* __restrict__ o)
{
    int idx = blockIdx.x * 256 + threadIdx.x;
    if (idx >= HB * CC * HW2) return;
    int xx = idx & 127;
    int yy = (idx >> 7) & 127;
    int bc = idx >> 14;
    const float* p = x + (size_t)bc * HW + (yy * 2) * 256 + xx * 2;
    o[idx] = 0.25f * (p[0] + p[1] + p[256] + p[257]);
}

// ---------------- q1 regrouping gather ----------------
__global__ void q1gather_kernel(const float* __restrict__ qt, float* __restrict__ qr)
{
    int idx = blockIdx.x * 256 + threadIdx.x;
    if (idx >= 16 * CC * HW2) return;
    int x = idx & 127;
    int y = (idx >> 7) & 127;
    int c = (idx >> 14) % CC;
    int img = idx / (CC * HW2);
    int whp = y >> 3, yy = y & 7, wwp = x >> 3, xx = x & 7;
    int k = img & 3, b = img >> 2;
    int wh = 8 * k + (whp >> 1);
    int ww = ((whp & 1) << 4) + wwp;
    int sy = wh * 8 + yy, sx = ww * 8 + xx;
    qr[idx] = qt[((size_t)b * CC + c) * HW + sy * 256 + sx];
}

// ---------------- shifted-window cosine attention ----------------
__global__ void winattn_kernel(const float* __restrict__ qg, const float* __restrict__ kvg,
                               const float* __restrict__ rpbt, const float* __restrict__ temp1,
                               float* __restrict__ outg)
{
    extern __shared__ float smw[];
    float* qs = smw;
    float* ks = qs + 192 * 64;
    float* vs = ks + 192 * 64;
    float* os = vs + 192 * 64;
    float* at = os + 192 * 64;
    float* inq = at + 64 * 65;
    float* ink = inq + 384;

    int win = blockIdx.x;
    int img = win >> 8;
    int loc = win & 255;
    int whp = loc >> 4, wwp = loc & 15;
    int kwin = win >> 2;
    int bk = kwin >> 8;
    int loc2 = kwin & 255;
    int gh = loc2 >> 4, gw = loc2 & 15;
    int tid = threadIdx.x;

    for (int e = tid; e < 192 * 64; e += 256) {
        int c = e >> 6, t = e & 63;
        int yy = t >> 3, xx = t & 7;
        int y = (whp * 8 + yy + 4) & 127;
        int x = (wwp * 8 + xx + 4) & 127;
        qs[e] = qg[((size_t)img * CC + c) * HW2 + y * 128 + x];
    }
    for (int e = tid; e < 192 * 64; e += 256) {
        int c = e >> 6, t = e & 63;
        int yy = t >> 3, xx = t & 7;
        int y = (gh * 8 + yy + 4) & 127;
        int x = (gw * 8 + xx + 4) & 127;
        size_t base = ((size_t)bk * 2 * CC + c) * HW2 + y * 128 + x;
        ks[e] = kvg[base];
        vs[e] = kvg[base + (size_t)CC * HW2];
    }
    __syncthreads();

    for (int e = tid; e < 384; e += 256) {
        int h = e >> 6, t = e & 63;
        float sq = 0.f, sk = 0.f;
#pragma unroll
        for (int i = 0; i < 32; i++) {
            float a = qs[(h * 32 + i) * 64 + t]; sq += a * a;
            float b = ks[(h * 32 + i) * 64 + t]; sk += b * b;
        }
        inq[e] = 1.f / fmaxf(sqrtf(sq), 1e-12f);
        ink[e] = 1.f / fmaxf(sqrtf(sk), 1e-12f);
    }
    __syncthreads();

    for (int h = 0; h < HEADS; h++) {
        float tmp = temp1[h];
        for (int e = tid; e < 4096; e += 256) {
            int n = e >> 6, m = e & 63;
            const float* qp = qs + (h * 32) * 64 + n;
            const float* kp = ks + (h * 32) * 64 + m;
            float s = 0.f;
#pragma unroll
            for (int i = 0; i < 32; i++) s += qp[i * 64] * kp[i * 64];
            s = s * inq[h * 64 + n] * ink[h * 64 + m] * tmp;
            int yn = n >> 3, xn = n & 7, ym = m >> 3, xm = m & 7;
            int ridx = (yn - ym + 7) * 15 + (xn - xm + 7);
            s += rpbt[ridx * HEADS + h];
            int pyn = gh * 8 + yn, pxn = gw * 8 + xn;
            int pym = gh * 8 + ym, pxm = gw * 8 + xm;
            int ln = (pyn < 120 ? 0 : (pyn < 124 ? 1 : 2)) * 3 + (pxn < 120 ? 0 : (pxn < 124 ? 1 : 2));
            int lm = (pym < 120 ? 0 : (pym < 124 ? 1 : 2)) * 3 + (pxm < 120 ? 0 : (pxm < 124 ? 1 : 2));
            if (ln != lm) s -= 100.f;
            at[n * 65 + m] = s;
        }
        __syncthreads();
        {
            int wid = tid >> 5, lane = tid & 31;
            for (int r = wid; r < 64; r += 8) {
                float v0 = at[r * 65 + lane], v1 = at[r * 65 + lane + 32];
                float mx = fmaxf(v0, v1);
#pragma unroll
                for (int o = 16; o; o >>= 1) mx = fmaxf(mx, __shfl_xor_sync(0xffffffffu, mx, o));
                v0 = expf(v0 - mx);
                v1 = expf(v1 - mx);
                float su = v0 + v1;
#pragma unroll
                for (int o = 16; o; o >>= 1) su += __shfl_xor_sync(0xffffffffu, su, o);
                float inv = 1.f / su;
                at[r * 65 + lane] = v0 * inv;
                at[r * 65 + lane + 32] = v1 * inv;
            }
        }
        __syncthreads();
        for (int e = tid; e < 2048; e += 256) {
            int i = e >> 6, n = e & 63;
            const float* ap = at + n * 65;
            const float* vp = vs + (h * 32 + i) * 64;
            float s = 0.f;
#pragma unroll
            for (int m = 0; m < 64; m++) s += ap[m] * vp[m];
            os[(h * 32 + i) * 64 + n] = s;
        }
        __syncthreads();
    }
    for (int e = tid; e < 192 * 64; e += 256) {
        int c = e >> 6, t = e & 63;
        outg[(size_t)c * 262144 + (size_t)win * 64 + t] = os[e];
    }
}

// ---------------- proj1 result scatter-add ----------------
__global__ void scatter1_kernel(const float* __restrict__ pin, float* __restrict__ out)
{
    int idx = blockIdx.x * 256 + threadIdx.x;
    if (idx >= CC * 262144) return;
    int p = idx & 262143;
    int cc = idx >> 18;
    int w = p >> 6;
    int t = p & 63;
    int yy = t >> 3, xx = t & 7;
    int b = w >> 10;
    int wh = (w >> 5) & 31;
    int wn = w & 31;
    int y = (wh * 8 + yy + 4) & 255;
    int x = (wn * 8 + xx + 4) & 255;
    out[((size_t)b * CC + cc) * HW + y * 256 + x] += pin[idx];
}

// ==================================================================
extern "C" void kernel_launch(void* const* d_in, const int* in_sizes, int n_in,
                              void* d_out, int out_size)
{
    const float* x      = (const float*)d_in[0];
    const float* Wq0    = (const float*)d_in[1];
    const float* Wqdw0  = (const float*)d_in[2];
    const float* Wkv0   = (const float*)d_in[3];
    const float* Wkvdw0 = (const float*)d_in[4];
    const float* Wq1    = (const float*)d_in[5];
    const float* Wqdw1  = (const float*)d_in[6];
    const float* Wkv1   = (const float*)d_in[7];
    const float* Wkvdw1 = (const float*)d_in[8];
    const float* Wproj0 = (const float*)d_in[9];
    const float* Wproj1 = (const float*)d_in[10];
    const float* temp0  = (const float*)d_in[11];
    const float* temp1  = (const float*)d_in[12];
    const float* rpbt   = (const float*)d_in[13];
    const float* Wds    = (const float*)d_in[14];
    float* out = (float*)d_out;

    float *A, *B, *invq, *invk, *Sb, *A0, *part;
    cudaGetSymbolAddress((void**)&A, g_A);
    cudaGetSymbolAddress((void**)&B, g_B);
    cudaGetSymbolAddress((void**)&invq, g_invq);
    cudaGetSymbolAddress((void**)&invk, g_invk);
    cudaGetSymbolAddress((void**)&Sb, g_S);
    cudaGetSymbolAddress((void**)&A0, g_A0);
    cudaGetSymbolAddress((void**)&part, g_part);

    const size_t OFF50 = 50331648;
    float* A2  = A + OFF50;
    float* B12 = B + 12582912;
    float* B25 = B + 25165824;
    float* B50 = B + 50331648;

    // ---------- level 0 ----------
    mma_gemm_kernel<<<dim3(512, 3, 4), 256>>>(x, Wkv0, nullptr, A, CC, 2 * CC, HW);
    dw3_kernel<<<(4 * 2 * CC * HW) / 256, 256>>>(A, Wkvdw0, B, 2 * CC, 256, 256, 4 * 2 * CC * HW);
    mma_gemm_kernel<<<dim3(512, 2, 4), 256>>>(x, Wq0, nullptr, A, CC, CC, HW);
    dw3_kernel<<<(4 * CC * HW) / 256, 256>>>(A, Wqdw0, A2, CC, 256, 256, 4 * CC * HW);
    rownorm_kernel<<<768, 256>>>(A2, CC, invq);
    rownorm_kernel<<<768, 256>>>(B, 2 * CC, invk);
    s_accum_kernel<<<dim3(32, 24), 256>>>(A2, B, part);
    s_reduce_kernel<<<96, 256>>>(part, Sb);
    softmax0_kernel<<<24, dim3(32, 32)>>>(Sb, invq, invk, temp0, A0);
    out0n_kernel<<<dim3(256, 24), 256>>>(A0, B, A);
    mma_gemm_kernel<<<dim3(512, 2, 4), 256>>>(A, Wproj0, nullptr, out, CC, CC, HW);

    // ---------- level 1 ----------
    avgpool_kernel<<<(4 * CC * HW2) / 256, 256>>>(x, B);
    mma_gemm_kernel<<<dim3(128, 2, 4), 256>>>(B, Wds, B, B12, CC, CC, HW2);
    mma_gemm_kernel<<<dim3(128, 3, 4), 256>>>(B12, Wkv1, nullptr, B25, CC, 2 * CC, HW2);
    dw3_kernel<<<(4 * 2 * CC * HW2) / 256, 256>>>(B25, Wkvdw1, B50, 2 * CC, 128, 128, 4 * 2 * CC * HW2);
    mma_gemm_kernel<<<dim3(512, 2, 4), 256>>>(x, Wq1, nullptr, A, CC, CC, HW);
    q1gather_kernel<<<(16 * CC * HW2) / 256, 256>>>(A, A2);
    dw3_kernel<<<(16 * CC * HW2) / 256, 256>>>(A2, Wqdw1, A, CC, 128, 128, 16 * CC * HW2);
    {
        int smemBytes = (4 * 192 * 64 + 64 * 65 + 2 * 384) * 4;
        cudaFuncSetAttribute(winattn_kernel, cudaFuncAttributeMaxDynamicSharedMemorySize, smemBytes);
        winattn_kernel<<<4096, 256, smemBytes>>>(A, B50, rpbt, temp1, B);
    }
    mma_gemm_kernel<<<dim3(2048, 2, 1), 256>>>(B, Wproj1, nullptr, A2, CC, CC, 262144);
    scatter1_kernel<<<(CC * 262144) / 256, 256>>>(A2, out);
}

// round 6
// speedup vs baseline: 1.6883x; 1.2950x over previous
#include <cuda_runtime.h>
#include <cuda_bf16.h>
#include <math.h>
#include <stdint.h>

#define HB 4
#define CC 192
#define HW 65536
#define HW2 16384
#define HEADS 6
#define CHD 32

typedef unsigned short u16;

// ---------------- static scratch ----------------
__device__ float g_A[100663296];      // 402 MB
__device__ float g_B[100663296];      // 402 MB
__device__ u16   g_Xh[50331648];      // x bf16 hi plane (96 MB)
__device__ u16   g_Xl[50331648];      // x bf16 lo plane
__device__ u16   g_Wh[393216];        // all weights, padded rows, hi
__device__ u16   g_Wl[393216];
__device__ float g_invq[768];
__device__ float g_invk[768];
__device__ float g_S[24 * 1024];
__device__ float g_A0[24 * 1024];
__device__ float g_part[32 * 24 * 1024];

// weight plane offsets (u16 units), rows padded to grid.y*128, IC=192
#define WO_Q0    0         // 256 rows
#define WO_KV0   49152     // 384 rows
#define WO_Q1    122880    // 256
#define WO_KV1   172032    // 384
#define WO_P0    245760    // 256
#define WO_P1    294912    // 256
#define WO_DS    344064    // 256

// ================= helpers =================
__device__ __forceinline__ u16 bfb(float v) {
    __nv_bfloat16 b = __float2bfloat16(v);
    return *(u16*)&b;
}
__device__ __forceinline__ float bff(u16 s) {
    __nv_bfloat16 b = *(__nv_bfloat16*)&s;
    return __bfloat162float(b);
}
__device__ __forceinline__ uint32_t smem_u32(const void* p) {
    uint32_t a;
    asm("{ .reg .u64 t; cvta.to.shared.u64 t, %1; cvt.u32.u64 %0, t; }" : "=r"(a) : "l"(p));
    return a;
}
__device__ __forceinline__ void mma16816(float* d, const uint32_t* a, const uint32_t* b) {
    asm volatile(
        "mma.sync.aligned.m16n8k16.row.col.f32.bf16.bf16.f32 "
        "{%0,%1,%2,%3}, {%4,%5,%6,%7}, {%8,%9}, {%0,%1,%2,%3};"
        : "+f"(d[0]), "+f"(d[1]), "+f"(d[2]), "+f"(d[3])
        : "r"(a[0]), "r"(a[1]), "r"(a[2]), "r"(a[3]), "r"(b[0]), "r"(b[1]));
}
__device__ __forceinline__ void ldsm4(uint32_t* r, uint32_t addr) {
    asm volatile("ldmatrix.sync.aligned.m8n8.x4.shared.b16 {%0,%1,%2,%3}, [%4];"
        : "=r"(r[0]), "=r"(r[1]), "=r"(r[2]), "=r"(r[3]) : "r"(addr));
}
__device__ __forceinline__ void ldsm4t(uint32_t* r, uint32_t addr) {
    asm volatile("ldmatrix.sync.aligned.m8n8.x4.trans.shared.b16 {%0,%1,%2,%3}, [%4];"
        : "=r"(r[0]), "=r"(r[1]), "=r"(r[2]), "=r"(r[3]) : "r"(addr));
}
__device__ __forceinline__ void cpa16(uint32_t dst, const void* src) {
    asm volatile("cp.async.cg.shared.global [%0], [%1], 16;" :: "r"(dst), "l"(src));
}
#define CP_COMMIT() asm volatile("cp.async.commit_group;" ::: "memory")
#define CP_WAIT0()  asm volatile("cp.async.wait_group 0;" ::: "memory")
#define CP_WAIT1()  asm volatile("cp.async.wait_group 1;" ::: "memory")

// ---------------- conversion kernels ----------------
__global__ void cvtx_kernel(const float* __restrict__ src, u16* __restrict__ hi,
                            u16* __restrict__ lo, int n4)
{
    int i = blockIdx.x * 256 + threadIdx.x;
    if (i >= n4) return;
    float4 v = *(const float4*)(src + (size_t)i * 4);
    u16 h0 = bfb(v.x), h1 = bfb(v.y), h2 = bfb(v.z), h3 = bfb(v.w);
    ushort4 hh = {h0, h1, h2, h3};
    ushort4 ll = {bfb(v.x - bff(h0)), bfb(v.y - bff(h1)), bfb(v.z - bff(h2)), bfb(v.w - bff(h3))};
    *(ushort4*)(hi + (size_t)i * 4) = hh;
    *(ushort4*)(lo + (size_t)i * 4) = ll;
}

__global__ void cvtw_kernel(const float* __restrict__ src, u16* __restrict__ hi,
                            u16* __restrict__ lo, int OC, int rows)
{
    int i = blockIdx.x * 256 + threadIdx.x;
    if (i >= rows * CC) return;
    int r = i / CC;
    float v = (r < OC) ? src[i] : 0.f;
    u16 h = bfb(v);
    hi[i] = h;
    lo[i] = bfb(v - bff(h));
}

// ---------------- pipelined bf16 hi/lo split GEMM ----------------
// Y[g][oc][p] = sum_ic W[oc][ic] X[g][ic][p] (+resid)
// grid(P/128, OCpad/128, G), 256 threads.
#define ASTR 40     // A smem k-stride (u16): 80B rows, 16B aligned, LDSM conflict-free
#define BSTR 136    // B smem p-stride (u16): 272B rows
#define A_BUF_U (2 * 128 * ASTR)   // 10240 u16 per buffer (2 planes)
#define B_BUF_U (2 * 32 * BSTR)    // 8704
#define GEMM_SMEM ((2 * A_BUF_U + 2 * B_BUF_U) * 2)   // 75776 B

__global__ void __launch_bounds__(256, 2)
mma_gemm2(const u16* __restrict__ Xh, const u16* __restrict__ Xl,
          const u16* __restrict__ Wh, const u16* __restrict__ Wl,
          const float* __restrict__ resid, float* __restrict__ Yf,
          u16* __restrict__ Yh, u16* __restrict__ Yl,
          int OC, int P)
{
    extern __shared__ u16 smu[];
    const uint32_t sbA = smem_u32(smu);
    const uint32_t sbB = sbA + 2 * A_BUF_U * 2;

    const int tid = threadIdx.x;
    const int warp = tid >> 5, lane = tid & 31;
    const int g4 = lane >> 2, t4 = lane & 3;
    const int wm = warp >> 1, wn = warp & 1;
    const int gz = blockIdx.z;
    const int oc0 = blockIdx.y * 128;
    const int p0 = blockIdx.x * 128;
    const size_t xoff = (size_t)gz * CC * P + p0;

    float acc[2][8][4];
#pragma unroll
    for (int mt = 0; mt < 2; mt++)
#pragma unroll
        for (int nt = 0; nt < 8; nt++)
#pragma unroll
            for (int e = 0; e < 4; e++) acc[mt][nt][e] = 0.f;

    auto prefetch = [&](int kc, int buf) {
        const int kbase = kc * 32;
        const uint32_t abase = sbA + buf * A_BUF_U * 2;
#pragma unroll
        for (int i = 0; i < 4; i++) {
            int op = tid + i * 256;
            int pl = op >> 9, rem = op & 511;
            int row = rem >> 2, cq = rem & 3;
            const u16* src = (pl ? Wl : Wh) + (size_t)(oc0 + row) * CC + kbase + cq * 8;
            uint32_t dst = abase + (uint32_t)((pl * 128 + row) * ASTR + cq * 8) * 2;
            cpa16(dst, src);
        }
        const uint32_t bbase = sbB + buf * B_BUF_U * 2;
#pragma unroll
        for (int i = 0; i < 4; i++) {
            int op = tid + i * 256;
            int pl = op >> 9, rem = op & 511;
            int row = rem >> 4, cq = rem & 15;
            const u16* src = (pl ? Xl : Xh) + xoff + (size_t)(kbase + row) * P + cq * 8;
            uint32_t dst = bbase + (uint32_t)((pl * 32 + row) * BSTR + cq * 8) * 2;
            cpa16(dst, src);
        }
    };

    prefetch(0, 0);
    CP_COMMIT();

    const int KC = CC / 32;   // 6
    for (int kc = 0; kc < KC; kc++) {
        if (kc + 1 < KC) {
            prefetch(kc + 1, (kc + 1) & 1);
            CP_COMMIT();
            CP_WAIT1();
        } else {
            CP_WAIT0();
        }
        __syncthreads();

        const int buf = kc & 1;
        const uint32_t aoff = sbA + buf * A_BUF_U * 2;
        const uint32_t boff = sbB + buf * B_BUF_U * 2;
#pragma unroll
        for (int ks = 0; ks < 2; ks++) {
            const int k0 = ks * 16;
            uint32_t ah[2][4], al[2][4];
#pragma unroll
            for (int mt = 0; mt < 2; mt++) {
                int mrow = wm * 32 + mt * 16 + (lane & 15);
                int kk = k0 + ((lane & 16) >> 1);
                ldsm4(ah[mt], aoff + (uint32_t)(mrow * ASTR + kk) * 2);
                ldsm4(al[mt], aoff + (uint32_t)((128 + mrow) * ASTR + kk) * 2);
            }
#pragma unroll
            for (int np = 0; np < 4; np++) {
                int krow = k0 + (lane & 15);
                int ncol = wn * 64 + np * 16 + ((lane & 16) >> 1);
                uint32_t bh[4], bl[4];
                ldsm4t(bh, boff + (uint32_t)(krow * BSTR + ncol) * 2);
                ldsm4t(bl, boff + (uint32_t)((32 + krow) * BSTR + ncol) * 2);
#pragma unroll
                for (int half = 0; half < 2; half++) {
                    int nt = np * 2 + half;
                    uint32_t* bhp = bh + half * 2;
                    uint32_t* blp = bl + half * 2;
                    mma16816(acc[0][nt], ah[0], bhp);
                    mma16816(acc[1][nt], ah[1], bhp);
                    mma16816(acc[0][nt], ah[0], blp);
                    mma16816(acc[1][nt], ah[1], blp);
                    mma16816(acc[0][nt], al[0], bhp);
                    mma16816(acc[1][nt], al[1], bhp);
                }
            }
        }
        __syncthreads();
    }

    // ---- epilogue ----
#pragma unroll
    for (int mt = 0; mt < 2; mt++) {
        int r0 = oc0 + wm * 32 + mt * 16 + g4;
#pragma unroll
        for (int nt = 0; nt < 8; nt++) {
            int p = p0 + wn * 64 + nt * 8 + t4 * 2;
#pragma unroll
            for (int hrow = 0; hrow < 2; hrow++) {
                int r = r0 + hrow * 8;
                if (r < OC) {
                    size_t o = ((size_t)gz * OC + r) * P + p;
                    float v0 = acc[mt][nt][hrow * 2 + 0];
                    float v1 = acc[mt][nt][hrow * 2 + 1];
                    if (resid) { v0 += resid[o]; v1 += resid[o + 1]; }
                    if (Yf) { Yf[o] = v0; Yf[o + 1] = v1; }
                    if (Yh) {
                        u16 h0 = bfb(v0), h1 = bfb(v1);
                        Yh[o] = h0; Yh[o + 1] = h1;
                        Yl[o] = bfb(v0 - bff(h0)); Yl[o + 1] = bfb(v1 - bff(h1));
                    }
                }
            }
        }
    }
}

// ---------------- depthwise 3x3 (4 px / thread) ----------------
__global__ void dw3v_kernel(const float* __restrict__ in, const float* __restrict__ w9,
                            float* __restrict__ out, int C, int Hn, int Wn, int total4)
{
    int idx = blockIdx.x * 256 + threadIdx.x;
    if (idx >= total4) return;
    int wq = Wn >> 2;
    int xg = (idx % wq) << 2;
    int t = idx / wq;                 // bc*Hn + y
    int y = t % Hn;
    int c = (t / Hn) % C;
    const float* wp = w9 + c * 9;
    const float* rowc = in + (size_t)t * Wn;
    float a0 = 0.f, a1 = 0.f, a2 = 0.f, a3 = 0.f;
#pragma unroll
    for (int dy = -1; dy <= 1; dy++) {
        int yy = y + dy;
        if ((unsigned)yy >= (unsigned)Hn) continue;
        const float* r = rowc + (ptrdiff_t)dy * Wn;
        float4 v = *(const float4*)(r + xg);
        float left = (xg > 0) ? r[xg - 1] : 0.f;
        float right = (xg + 4 < Wn) ? r[xg + 4] : 0.f;
        float w0 = wp[(dy + 1) * 3], w1 = wp[(dy + 1) * 3 + 1], w2 = wp[(dy + 1) * 3 + 2];
        a0 += w0 * left + w1 * v.x + w2 * v.y;
        a1 += w0 * v.x + w1 * v.y + w2 * v.z;
        a2 += w0 * v.y + w1 * v.z + w2 * v.w;
        a3 += w0 * v.z + w1 * v.w + w2 * right;
    }
    *(float4*)(out + (size_t)t * Wn + xg) = make_float4(a0, a1, a2, a3);
}

// ---------------- level-0 row norms ----------------
__global__ void rownorm_kernel(const float* __restrict__ base, int chanPerBatch,
                               float* __restrict__ inv)
{
    int row = blockIdx.x;
    int b = row / CC, c = row % CC;
    const float* p = base + ((size_t)b * chanPerBatch + c) * HW;
    float s = 0.f;
    for (int i = threadIdx.x; i < HW; i += 256) { float v = p[i]; s += v * v; }
    __shared__ float red[256];
    red[threadIdx.x] = s;
    __syncthreads();
    for (int o = 128; o; o >>= 1) {
        if (threadIdx.x < o) red[threadIdx.x] += red[threadIdx.x + o];
        __syncthreads();
    }
    if (threadIdx.x == 0) inv[row] = 1.f / fmaxf(sqrtf(red[0]), 1e-12f);
}

// ---------------- level-0 S = q k^T ----------------
__global__ void s_accum_kernel(const float* __restrict__ q, const float* __restrict__ kv,
                               float* __restrict__ part)
{
    int bh = blockIdx.y;
    int b = bh / HEADS, h = bh % HEADS;
    const float* qb = q + ((size_t)b * CC + h * CHD) * HW;
    const float* kb = kv + ((size_t)b * 2 * CC + h * CHD) * HW;
    int n0 = blockIdx.x * 2048;
    __shared__ float qt[32][65], kt[32][65];
    float acc[4] = {0.f, 0.f, 0.f, 0.f};
    int tid = threadIdx.x;
    for (int ns = 0; ns < 2048; ns += 64) {
#pragma unroll
        for (int r = 0; r < 8; r++) {
            int e = tid + r * 256;
            int c = e >> 6, nn = e & 63;
            qt[c][nn] = qb[(size_t)c * HW + n0 + ns + nn];
            kt[c][nn] = kb[(size_t)c * HW + n0 + ns + nn];
        }
        __syncthreads();
#pragma unroll
        for (int i = 0; i < 4; i++) {
            int pr = i * 256 + tid;
            int c = pr >> 5, d = pr & 31;
            float a = 0.f;
#pragma unroll
            for (int kk = 0; kk < 64; kk++) a += qt[c][kk] * kt[d][kk];
            acc[i] += a;
        }
        __syncthreads();
    }
#pragma unroll
    for (int i = 0; i < 4; i++) {
        int pr = i * 256 + tid;
        part[((size_t)blockIdx.x * 24 + bh) * 1024 + pr] = acc[i];
    }
}

__global__ void s_reduce_kernel(const float* __restrict__ part, float* __restrict__ S)
{
    int idx = blockIdx.x * 256 + threadIdx.x;
    float s = 0.f;
    for (int ck = 0; ck < 32; ck++) s += part[(size_t)ck * 24576 + idx];
    S[idx] = s;
}

// ---------------- level-0 softmax ----------------
__global__ void softmax0_kernel(const float* __restrict__ S, const float* __restrict__ invq,
                                const float* __restrict__ invk, const float* __restrict__ temp0,
                                float* __restrict__ A)
{
    int bh = blockIdx.x;
    int b = bh / HEADS, h = bh % HEADS;
    int c = threadIdx.y, d = threadIdx.x;
    float v = S[bh * 1024 + c * 32 + d] * invq[b * CC + h * CHD + c] *
              invk[b * CC + h * CHD + d] * temp0[h];
    float m = v;
#pragma unroll
    for (int o = 16; o; o >>= 1) m = fmaxf(m, __shfl_xor_sync(0xffffffffu, m, o));
    float e = expf(v - m);
    float s = e;
#pragma unroll
    for (int o = 16; o; o >>= 1) s += __shfl_xor_sync(0xffffffffu, s, o);
    A[bh * 1024 + c * 32 + d] = e / s;
}

// ---------------- level-0 out = A @ v -> bf16 planes ----------------
__global__ void out0n_kernel(const float* __restrict__ A, const float* __restrict__ kv,
                             u16* __restrict__ oh, u16* __restrict__ ol)
{
    int bh = blockIdx.y;
    int b = bh / HEADS, h = bh % HEADS;
    __shared__ float As[32][33];
    int tid = threadIdx.x;
    for (int e = tid; e < 1024; e += 256) As[e >> 5][e & 31] = A[bh * 1024 + e];
    __syncthreads();
    int n = blockIdx.x * 256 + tid;
    const float* vb = kv + ((size_t)b * 2 * CC + CC + h * CHD) * HW + n;
    float vr[32];
#pragma unroll
    for (int d = 0; d < 32; d++) vr[d] = vb[(size_t)d * HW];
    size_t ob = ((size_t)b * CC + h * CHD) * HW + n;
#pragma unroll
    for (int c = 0; c < 32; c++) {
        float s = 0.f;
#pragma unroll
        for (int d = 0; d < 32; d++) s += As[c][d] * vr[d];
        u16 hv = bfb(s);
        oh[ob + (size_t)c * HW] = hv;
        ol[ob + (size_t)c * HW] = bfb(s - bff(hv));
    }
}

// ---------------- avg pool 2x2 (fp32 + planes) ----------------
__global__ void avgpool_kernel(const float* __restrict__ x, float* __restrict__ o,
                               u16* __restrict__ oh, u16* __restrict__ ol)
{
    int idx = blockIdx.x * 256 + threadIdx.x;
    if (idx >= HB * CC * HW2) return;
    int xx = idx & 127;
    int yy = (idx >> 7) & 127;
    int bc = idx >> 14;
    const float* p = x + (size_t)bc * HW + (yy * 2) * 256 + xx * 2;
    float v = 0.25f * (p[0] + p[1] + p[256] + p[257]);
    o[idx] = v;
    u16 h = bfb(v);
    oh[idx] = h;
    ol[idx] = bfb(v - bff(h));
}

// ---------------- q1 regrouping gather ----------------
__global__ void q1gather_kernel(const float* __restrict__ qt, float* __restrict__ qr)
{
    int idx = blockIdx.x * 256 + threadIdx.x;
    if (idx >= 16 * CC * HW2) return;
    int x = idx & 127;
    int y = (idx >> 7) & 127;
    int c = (idx >> 14) % CC;
    int img = idx / (CC * HW2);
    int whp = y >> 3, yy = y & 7, wwp = x >> 3, xx = x & 7;
    int k = img & 3, b = img >> 2;
    int wh = 8 * k + (whp >> 1);
    int ww = ((whp & 1) << 4) + wwp;
    int sy = wh * 8 + yy, sx = ww * 8 + xx;
    qr[idx] = qt[((size_t)b * CC + c) * HW + sy * 256 + sx];
}

// ---------------- shifted-window cosine attention -> planes ----------------
__global__ void winattn_kernel(const float* __restrict__ qg, const float* __restrict__ kvg,
                               const float* __restrict__ rpbt, const float* __restrict__ temp1,
                               u16* __restrict__ oh, u16* __restrict__ ol)
{
    extern __shared__ float smw[];
    float* qs = smw;
    float* ks = qs + 192 * 64;
    float* vs = ks + 192 * 64;
    float* os = vs + 192 * 64;
    float* at = os + 192 * 64;
    float* inq = at + 64 * 65;
    float* ink = inq + 384;

    int win = blockIdx.x;
    int img = win >> 8;
    int loc = win & 255;
    int whp = loc >> 4, wwp = loc & 15;
    int kwin = win >> 2;
    int bk = kwin >> 8;
    int loc2 = kwin & 255;
    int gh = loc2 >> 4, gw = loc2 & 15;
    int tid = threadIdx.x;

    for (int e = tid; e < 192 * 64; e += 256) {
        int c = e >> 6, t = e & 63;
        int yy = t >> 3, xx = t & 7;
        int y = (whp * 8 + yy + 4) & 127;
        int x = (wwp * 8 + xx + 4) & 127;
        qs[e] = qg[((size_t)img * CC + c) * HW2 + y * 128 + x];
    }
    for (int e = tid; e < 192 * 64; e += 256) {
        int c = e >> 6, t = e & 63;
        int yy = t >> 3, xx = t & 7;
        int y = (gh * 8 + yy + 4) & 127;
        int x = (gw * 8 + xx + 4) & 127;
        size_t base = ((size_t)bk * 2 * CC + c) * HW2 + y * 128 + x;
        ks[e] = kvg[base];
        vs[e] = kvg[base + (size_t)CC * HW2];
    }
    __syncthreads();

    for (int e = tid; e < 384; e += 256) {
        int h = e >> 6, t = e & 63;
        float sq = 0.f, sk = 0.f;
#pragma unroll
        for (int i = 0; i < 32; i++) {
            float a = qs[(h * 32 + i) * 64 + t]; sq += a * a;
            float b = ks[(h * 32 + i) * 64 + t]; sk += b * b;
        }
        inq[e] = 1.f / fmaxf(sqrtf(sq), 1e-12f);
        ink[e] = 1.f / fmaxf(sqrtf(sk), 1e-12f);
    }
    __syncthreads();

    for (int h = 0; h < HEADS; h++) {
        float tmp = temp1[h];
        for (int e = tid; e < 4096; e += 256) {
            int n = e >> 6, m = e & 63;
            const float* qp = qs + (h * 32) * 64 + n;
            const float* kp = ks + (h * 32) * 64 + m;
            float s = 0.f;
#pragma unroll
            for (int i = 0; i < 32; i++) s += qp[i * 64] * kp[i * 64];
            s = s * inq[h * 64 + n] * ink[h * 64 + m] * tmp;
            int yn = n >> 3, xn = n & 7, ym = m >> 3, xm = m & 7;
            int ridx = (yn - ym + 7) * 15 + (xn - xm + 7);
            s += rpbt[ridx * HEADS + h];
            int pyn = gh * 8 + yn, pxn = gw * 8 + xn;
            int pym = gh * 8 + ym, pxm = gw * 8 + xm;
            int ln = (pyn < 120 ? 0 : (pyn < 124 ? 1 : 2)) * 3 + (pxn < 120 ? 0 : (pxn < 124 ? 1 : 2));
            int lm = (pym < 120 ? 0 : (pym < 124 ? 1 : 2)) * 3 + (pxm < 120 ? 0 : (pxm < 124 ? 1 : 2));
            if (ln != lm) s -= 100.f;
            at[n * 65 + m] = s;
        }
        __syncthreads();
        {
            int wid = tid >> 5, lane = tid & 31;
            for (int r = wid; r < 64; r += 8) {
                float v0 = at[r * 65 + lane], v1 = at[r * 65 + lane + 32];
                float mx = fmaxf(v0, v1);
#pragma unroll
                for (int o = 16; o; o >>= 1) mx = fmaxf(mx, __shfl_xor_sync(0xffffffffu, mx, o));
                v0 = expf(v0 - mx);
                v1 = expf(v1 - mx);
                float su = v0 + v1;
#pragma unroll
                for (int o = 16; o; o >>= 1) su += __shfl_xor_sync(0xffffffffu, su, o);
                float inv = 1.f / su;
                at[r * 65 + lane] = v0 * inv;
                at[r * 65 + lane + 32] = v1 * inv;
            }
        }
        __syncthreads();
        for (int e = tid; e < 2048; e += 256) {
            int i = e >> 6, n = e & 63;
            const float* ap = at + n * 65;
            const float* vp = vs + (h * 32 + i) * 64;
            float s = 0.f;
#pragma unroll
            for (int m = 0; m < 64; m++) s += ap[m] * vp[m];
            os[(h * 32 + i) * 64 + n] = s;
        }
        __syncthreads();
    }
    for (int e = tid; e < 192 * 64; e += 256) {
        int c = e >> 6, t = e & 63;
        float v = os[e];
        u16 hv = bfb(v);
        size_t o = (size_t)c * 262144 + (size_t)win * 64 + t;
        oh[o] = hv;
        ol[o] = bfb(v - bff(hv));
    }
}

// ---------------- proj1 result scatter-add ----------------
__global__ void scatter1_kernel(const float* __restrict__ pin, float* __restrict__ out)
{
    int idx = blockIdx.x * 256 + threadIdx.x;
    if (idx >= CC * 262144) return;
    int p = idx & 262143;
    int cc = idx >> 18;
    int w = p >> 6;
    int t = p & 63;
    int yy = t >> 3, xx = t & 7;
    int b = w >> 10;
    int wh = (w >> 5) & 31;
    int wn = w & 31;
    int y = (wh * 8 + yy + 4) & 255;
    int x = (wn * 8 + xx + 4) & 255;
    out[((size_t)b * CC + cc) * HW + y * 256 + x] += pin[idx];
}

// ==================================================================
extern "C" void kernel_launch(void* const* d_in, const int* in_sizes, int n_in,
                              void* d_out, int out_size)
{
    const float* x      = (const float*)d_in[0];
    const float* Wq0    = (const float*)d_in[1];
    const float* Wqdw0  = (const float*)d_in[2];
    const float* Wkv0   = (const float*)d_in[3];
    const float* Wkvdw0 = (const float*)d_in[4];
    const float* Wq1    = (const float*)d_in[5];
    const float* Wqdw1  = (const float*)d_in[6];
    const float* Wkv1   = (const float*)d_in[7];
    const float* Wkvdw1 = (const float*)d_in[8];
    const float* Wproj0 = (const float*)d_in[9];
    const float* Wproj1 = (const float*)d_in[10];
    const float* temp0  = (const float*)d_in[11];
    const float* temp1  = (const float*)d_in[12];
    const float* rpbt   = (const float*)d_in[13];
    const float* Wds    = (const float*)d_in[14];
    float* out = (float*)d_out;

    float *A, *B, *invq, *invk, *Sb, *A0, *part;
    u16 *Xh, *Xl, *Wh, *Wl;
    cudaGetSymbolAddress((void**)&A, g_A);
    cudaGetSymbolAddress((void**)&B, g_B);
    cudaGetSymbolAddress((void**)&Xh, g_Xh);
    cudaGetSymbolAddress((void**)&Xl, g_Xl);
    cudaGetSymbolAddress((void**)&Wh, g_Wh);
    cudaGetSymbolAddress((void**)&Wl, g_Wl);
    cudaGetSymbolAddress((void**)&invq, g_invq);
    cudaGetSymbolAddress((void**)&invk, g_invk);
    cudaGetSymbolAddress((void**)&Sb, g_S);
    cudaGetSymbolAddress((void**)&A0, g_A0);
    cudaGetSymbolAddress((void**)&part, g_part);

    const size_t OFF50 = 50331648;
    float* A2 = A + OFF50;

    // level-1 buffer B layout (floats)
    float* poolF = B;                               // 12.58M
    u16* poolH = (u16*)(B + 12582912);
    u16* poolL = (u16*)(B + 12582912 + 6291456);
    u16* xdsH  = (u16*)(B + 25165824);
    u16* xdsL  = (u16*)(B + 31457280);
    float* kv1t = B + 37748736;
    float* kv1  = B + 62914560;
    // out0n planes reuse g_A front half; winattn planes reuse g_B front half
    u16* P0h = (u16*)A;
    u16* P0l = (u16*)(A + 25165824);
    u16* W1h = (u16*)B;
    u16* W1l = (u16*)(B + 25165824);

    cudaFuncSetAttribute(mma_gemm2, cudaFuncAttributeMaxDynamicSharedMemorySize, GEMM_SMEM);

    // ---- conversions ----
    cvtw_kernel<<<(256 * CC + 255) / 256, 256>>>(Wq0,    Wh + WO_Q0,  Wl + WO_Q0,  192, 256);
    cvtw_kernel<<<(384 * CC + 255) / 256, 256>>>(Wkv0,   Wh + WO_KV0, Wl + WO_KV0, 384, 384);
    cvtw_kernel<<<(256 * CC + 255) / 256, 256>>>(Wq1,    Wh + WO_Q1,  Wl + WO_Q1,  192, 256);
    cvtw_kernel<<<(384 * CC + 255) / 256, 256>>>(Wkv1,   Wh + WO_KV1, Wl + WO_KV1, 384, 384);
    cvtw_kernel<<<(256 * CC + 255) / 256, 256>>>(Wproj0, Wh + WO_P0,  Wl + WO_P0,  192, 256);
    cvtw_kernel<<<(256 * CC + 255) / 256, 256>>>(Wproj1, Wh + WO_P1,  Wl + WO_P1,  192, 256);
    cvtw_kernel<<<(256 * CC + 255) / 256, 256>>>(Wds,    Wh + WO_DS,  Wl + WO_DS,  192, 256);
    cvtx_kernel<<<49152, 256>>>(x, Xh, Xl, 12582912);

    // ---------- level 0 ----------
    mma_gemm2<<<dim3(512, 3, 4), 256, GEMM_SMEM>>>(Xh, Xl, Wh + WO_KV0, Wl + WO_KV0,
                                                   nullptr, A, nullptr, nullptr, 2 * CC, HW);
    dw3v_kernel<<<(4 * 2 * CC * HW / 4) / 256, 256>>>(A, Wkvdw0, B, 2 * CC, 256, 256, 4 * 2 * CC * HW / 4);
    mma_gemm2<<<dim3(512, 2, 4), 256, GEMM_SMEM>>>(Xh, Xl, Wh + WO_Q0, Wl + WO_Q0,
                                                   nullptr, A, nullptr, nullptr, CC, HW);
    dw3v_kernel<<<(4 * CC * HW / 4) / 256, 256>>>(A, Wqdw0, A2, CC, 256, 256, 4 * CC * HW / 4);
    rownorm_kernel<<<768, 256>>>(A2, CC, invq);
    rownorm_kernel<<<768, 256>>>(B, 2 * CC, invk);
    s_accum_kernel<<<dim3(32, 24), 256>>>(A2, B, part);
    s_reduce_kernel<<<96, 256>>>(part, Sb);
    softmax0_kernel<<<24, dim3(32, 32)>>>(Sb, invq, invk, temp0, A0);
    out0n_kernel<<<dim3(256, 24), 256>>>(A0, B, P0h, P0l);
    mma_gemm2<<<dim3(512, 2, 4), 256, GEMM_SMEM>>>(P0h, P0l, Wh + WO_P0, Wl + WO_P0,
                                                   nullptr, out, nullptr, nullptr, CC, HW);

    // ---------- level 1 ----------
    avgpool_kernel<<<(4 * CC * HW2) / 256, 256>>>(x, poolF, poolH, poolL);
    mma_gemm2<<<dim3(128, 2, 4), 256, GEMM_SMEM>>>(poolH, poolL, Wh + WO_DS, Wl + WO_DS,
                                                   poolF, nullptr, xdsH, xdsL, CC, HW2);
    mma_gemm2<<<dim3(128, 3, 4), 256, GEMM_SMEM>>>(xdsH, xdsL, Wh + WO_KV1, Wl + WO_KV1,
                                                   nullptr, kv1t, nullptr, nullptr, 2 * CC, HW2);
    dw3v_kernel<<<(4 * 2 * CC * HW2 / 4) / 256, 256>>>(kv1t, Wkvdw1, kv1, 2 * CC, 128, 128, 4 * 2 * CC * HW2 / 4);
    mma_gemm2<<<dim3(512, 2, 4), 256, GEMM_SMEM>>>(Xh, Xl, Wh + WO_Q1, Wl + WO_Q1,
                                                   nullptr, A, nullptr, nullptr, CC, HW);
    q1gather_kernel<<<(16 * CC * HW2) / 256, 256>>>(A, A2);
    dw3v_kernel<<<(16 * CC * HW2 / 4) / 256, 256>>>(A2, Wqdw1, A, CC, 128, 128, 16 * CC * HW2 / 4);
    {
        int smemBytes = (4 * 192 * 64 + 64 * 65 + 2 * 384) * 4;
        cudaFuncSetAttribute(winattn_kernel, cudaFuncAttributeMaxDynamicSharedMemorySize, smemBytes);
        winattn_kernel<<<4096, 256, smemBytes>>>(A, kv1, rpbt, temp1, W1h, W1l);
    }
    mma_gemm2<<<dim3(2048, 2, 1), 256, GEMM_SMEM>>>(W1h, W1l, Wh + WO_P1, Wl + WO_P1,
                                                    nullptr, A2, nullptr, nullptr, CC, 262144);
    scatter1_kernel<<<(CC * 262144) / 256, 256>>>(A2, out);
}